// round 11
// baseline (speedup 1.0000x reference)
#include <cuda_runtime.h>
#include <math.h>

#define NBINS 229
#define OUTF  88
#define MODEL 128
#define WSZ   30
#define WIN   61
#define TSEQ  1024
#define NTOK  4096
#define TPAD  1084            // 30 + 1024 + 30
#define PCOLS 176             // P1(88) | P2(88)
#define AT_TT 16              // tokens per attention block
#define AT_ROWS (AT_TT + 2*WSZ)   // 76 staged rows (real)
#define AT_ROWS_AL 79         // allocated rows (max read row = 15+3+60 = 78)
#define UPITCH 132            // padded u row (33 float4)
#define UP4 (UPITCH/4)
#define APITCH 18             // A row pitch (72B, 8-aligned for u64 reads)
#define PPITCH 17             // part row pitch
#define SCPITCH 62

// smem float offsets
#define SM_U    0
#define SM_P1   (AT_ROWS_AL * UPITCH)                 // 10428
#define SM_P1SZ 6840                                  // max(76*88=6688, 176*18+216*17=6840)
#define SM_P2   (SM_P1 + SM_P1SZ)                     // 17268
#define SM_SC   (SM_P2 + AT_ROWS * OUTF)              // 23956
#define SM_GC   (SM_SC + AT_TT * SCPITCH)             // 24948
#define SM_XL   (SM_GC + AT_TT * MODEL)               // 26996
#define SM_TOT  (SM_XL + AT_TT * OUTF)                // 28404 floats = 113616 B

// Output layout (floats): frame_pred, a_frame, onset_pred, a_onset, feat_pred
#define FRAME_OFF  0
#define AFRAME_OFF (NTOK*OUTF)
#define ONSET_OFF  (AFRAME_OFF + NTOK*WIN)
#define AONSET_OFF (ONSET_OFF + NTOK*OUTF)
#define FEAT_OFF   (AONSET_OFF + NTOK*WIN)

// Scratch (__device__ globals; zero-initialized at load — guard rows of
// g_uo/g_uc/g_p12 are never written, so they stay zero forever).
__device__ float g_go[NTOK * MODEL];
__device__ float g_uo[4 * TPAD * MODEL];
__device__ float g_uc[4 * TPAD * MODEL];
__device__ float g_p12[4 * TPAD * PCOLS];

__device__ __forceinline__ float tanh_fast(float x) {
    float y; asm("tanh.approx.f32 %0, %1;" : "=f"(y) : "f"(x)); return y;
}
__device__ __forceinline__ float sigmoid_fast(float x) {
    return 1.f / (1.f + __expf(-x));
}
__device__ __forceinline__ unsigned long long pkf2(float lo, float hi) {
    unsigned long long r;
    asm("mov.b64 %0, {%1, %2};" : "=l"(r) : "f"(lo), "f"(hi));
    return r;
}
__device__ __forceinline__ void fma2(unsigned long long& acc,
                                     unsigned long long a, unsigned long long b) {
    asm("fma.rn.f32x2 %0, %1, %2, %0;" : "+l"(acc) : "l"(a), "l"(b));
}
__device__ __forceinline__ float2 upk(unsigned long long v) {
    float2 r;
    asm("mov.b64 {%0, %1}, %2;" : "=f"(r.x), "=f"(r.y) : "l"(v));
    return r;
}
__device__ __forceinline__ float warp_sum(float v) {
    v += __shfl_xor_sync(0xFFFFFFFFu, v, 16);
    v += __shfl_xor_sync(0xFFFFFFFFu, v, 8);
    v += __shfl_xor_sync(0xFFFFFFFFu, v, 4);
    v += __shfl_xor_sync(0xFFFFFFFFu, v, 2);
    v += __shfl_xor_sync(0xFFFFFFFFu, v, 1);
    return v;
}
__device__ __forceinline__ float warp_max(float v) {
    v = fmaxf(v, __shfl_xor_sync(0xFFFFFFFFu, v, 16));
    v = fmaxf(v, __shfl_xor_sync(0xFFFFFFFFu, v, 8));
    v = fmaxf(v, __shfl_xor_sync(0xFFFFFFFFu, v, 4));
    v = fmaxf(v, __shfl_xor_sync(0xFFFFFFFFu, v, 2));
    v = fmaxf(v, __shfl_xor_sync(0xFFFFFFFFu, v, 1));
    return v;
}

// ---------------------------------------------------------------------------
// k1: mega projection GEMM  [NTOK x 229] @ [229 x 648], 2 cols per thread
// ---------------------------------------------------------------------------
#define K1_TT 16
__device__ __forceinline__ const float* k1_col_ptr(
    int j, int& stride,
    const float* Wf, const float* Wao, const float* Wac,
    const float* Wl1, const float* Wlc)
{
    if (j < 88)       { stride = OUTF;  return Wf + j; }
    else if (j < 216) { stride = MODEL; return Wao + (j - 88); }
    else if (j < 344) { stride = MODEL; return Wao + NBINS*MODEL + (j - 216); }
    else if (j < 472) { stride = MODEL; return Wac + 176*MODEL  + (j - 344); }
    else if (j < 560) { stride = OUTF;  return Wl1 + (j - 472); }
    else              { stride = OUTF;  return Wlc + 176*OUTF   + (j - 560); }
}

__device__ __forceinline__ void k1_store(
    int j, const float rv[K1_TT], int tok0, size_t row0,
    const float* bf, const float* bao, float* out)
{
    if (j < 88) {
        float bias = bf[j];
        #pragma unroll
        for (int tt = 0; tt < K1_TT; tt++)
            out[FEAT_OFF + (size_t)(tok0 + tt) * OUTF + j] = rv[tt] + bias;
    } else if (j < 216) {
        int m = j - 88;
        float bias = bao[m];
        #pragma unroll
        for (int tt = 0; tt < K1_TT; tt++)
            g_go[(size_t)(tok0 + tt) * MODEL + m] = rv[tt] + bias;
    } else if (j < 344) {
        int m = j - 216;
        #pragma unroll
        for (int tt = 0; tt < K1_TT; tt++)
            g_uo[(row0 + tt) * MODEL + m] = rv[tt];
    } else if (j < 472) {
        int m = j - 344;
        #pragma unroll
        for (int tt = 0; tt < K1_TT; tt++)
            g_uc[(row0 + tt) * MODEL + m] = rv[tt];
    } else if (j < 560) {
        int m = j - 472;
        #pragma unroll
        for (int tt = 0; tt < K1_TT; tt++)
            g_p12[(row0 + tt) * PCOLS + m] = rv[tt];
    } else {
        int m = j - 560 + 88;
        #pragma unroll
        for (int tt = 0; tt < K1_TT; tt++)
            g_p12[(row0 + tt) * PCOLS + m] = rv[tt];
    }
}

__global__ void __launch_bounds__(384) k1_proj(
    const float* __restrict__ spec,
    const float* __restrict__ Wf,  const float* __restrict__ bf,
    const float* __restrict__ Wao, const float* __restrict__ bao,
    const float* __restrict__ Wac,
    const float* __restrict__ Wl1,
    const float* __restrict__ Wlc,
    float* __restrict__ out)
{
    __shared__ __align__(16) float sh[NBINS][20];
    const int tok0 = blockIdx.x * K1_TT;

    for (int idx = threadIdx.x; idx < NBINS * K1_TT; idx += 384) {
        int tt = idx / NBINS;
        int k  = idx - tt * NBINS;
        sh[k][tt] = spec[(size_t)(tok0 + tt) * NBINS + k];
    }
    __syncthreads();

    const int j0 = threadIdx.x;
    if (j0 >= 324) return;
    const int j1 = j0 + 324;

    int st0, st1;
    const float* wp0 = k1_col_ptr(j0, st0, Wf, Wao, Wac, Wl1, Wlc);
    const float* wp1 = k1_col_ptr(j1, st1, Wf, Wao, Wac, Wl1, Wlc);

    unsigned long long acc0[8], acc1[8];
    #pragma unroll
    for (int p = 0; p < 8; p++) { acc0[p] = 0ull; acc1[p] = 0ull; }

    #pragma unroll 2
    for (int k = 0; k < NBINS; k++) {
        float w0 = *wp0; wp0 += st0;
        float w1 = *wp1; wp1 += st1;
        unsigned long long ww0 = pkf2(w0, w0);
        unsigned long long ww1 = pkf2(w1, w1);
        const unsigned long long* row = (const unsigned long long*)&sh[k][0];
        unsigned long long r[8];
        #pragma unroll
        for (int p = 0; p < 8; p++) r[p] = row[p];
        #pragma unroll
        for (int p = 0; p < 8; p++) fma2(acc0[p], r[p], ww0);
        #pragma unroll
        for (int p = 0; p < 8; p++) fma2(acc1[p], r[p], ww1);
    }

    const size_t row0 = (size_t)(tok0 >> 10) * TPAD + WSZ + (tok0 & (TSEQ - 1));
    float rv[K1_TT];
    #pragma unroll
    for (int p = 0; p < 8; p++) {
        float2 r = upk(acc0[p]);
        rv[2*p] = r.x; rv[2*p+1] = r.y;
    }
    k1_store(j0, rv, tok0, row0, bf, bao, out);
    #pragma unroll
    for (int p = 0; p < 8; p++) {
        float2 r = upk(acc1[p]);
        rv[2*p] = r.x; rv[2*p+1] = r.y;
    }
    k1_store(j1, rv, tok0, row0, bf, bao, out);
}

// ---------------------------------------------------------------------------
// k_fused: onset attention -> g_c/xl GEMM -> combine attention.
// 16 tokens/block (warp == token), 512 threads, all intermediates in smem.
// P2 has its own buffer and is prefetched in phase 1 (no post-GEMM staging).
// ---------------------------------------------------------------------------
__global__ void __launch_bounds__(512, 2) k_fused(
    const float* __restrict__ gvo,    // g_go [NTOK][128]
    const float* __restrict__ uo,     // g_uo
    const float* __restrict__ uc,     // g_uc
    const float* __restrict__ vo, const float* __restrict__ vc,
    const float* __restrict__ bl1,
    const float* __restrict__ Wac, const float* __restrict__ bac,
    const float* __restrict__ Wlc, const float* __restrict__ blc,
    const float* __restrict__ ppad,   // g_p12
    float* __restrict__ out)
{
    extern __shared__ __align__(16) float smem[];
    float* U  = smem + SM_U;     // u tile [79][132] (76 real rows)
    float* P1 = smem + SM_P1;    // p1 tile [76][88]  OR  A[176][18]+part[216][17]
    float* P2 = smem + SM_P2;    // p2 tile [76][88]
    float* sc = smem + SM_SC;    // [16][62]
    float* gc = smem + SM_GC;    // [16][128]
    float* xl = smem + SM_XL;    // [16][88]
    float* A    = P1;
    float* part = P1 + 176 * APITCH;

    const int tok0 = blockIdx.x * AT_TT;
    const int b    = tok0 >> 10;
    const int t0   = tok0 & (TSEQ - 1);
    const int tid  = threadIdx.x;
    const int warp = tid >> 5;
    const int lane = tid & 31;
    const int q    = lane >> 2;   // 16-dim slice
    const int wq   = lane & 3;    // window within group
    const int tok  = tok0 + warp;

    const size_t grow = (size_t)b * TPAD + t0;

    // ================= Phase 1: stage u_o, p1, p2; load onset g/v =================
    {
        const float4* usrc = (const float4*)(uo + grow * MODEL);
        float4* udst = (float4*)U;
        #pragma unroll
        for (int i = tid; i < AT_ROWS * 32; i += 512) {
            int r = i >> 5, c = i & 31;
            udst[r * UP4 + c] = usrc[i];
        }
        const float4* p1src = (const float4*)(ppad + grow * PCOLS);        // P1 col 0
        const float4* p2src = (const float4*)(ppad + grow * PCOLS + 88);   // P2 col 88
        float4* p1dst = (float4*)P1;
        float4* p2dst = (float4*)P2;
        #pragma unroll
        for (int i = tid; i < AT_ROWS * 22; i += 512) {
            int r = i / 22, c = i - r * 22;
            p1dst[i] = p1src[(size_t)r * 44 + c];
            p2dst[i] = p2src[(size_t)r * 44 + c];
        }
    }
    float4 gr[4], vr[4];
    {
        const float4* gp = (const float4*)(gvo + (size_t)tok * MODEL) + q * 4;
        const float4* vp = (const float4*)vo + q * 4;
        #pragma unroll
        for (int i = 0; i < 4; i++) { gr[i] = gp[i]; vr[i] = vp[i]; }
    }
    float* scrow = sc + warp * SCPITCH;
    __syncthreads();

    // ================= Phase 2: onset scores + softmax =================
    {
        const float4* ubase = (const float4*)U + (size_t)(warp + wq) * UP4 + q * 4;
        #pragma unroll 4
        for (int wb = 0; wb < 64; wb += 4) {
            const float4* ur = ubase + (size_t)wb * UP4;
            float pa = 0.f, pb = 0.f;
            #pragma unroll
            for (int i = 0; i < 4; i++) {
                float4 u = ur[i];
                pa += vr[i].x * tanh_fast(gr[i].x + u.x)
                    + vr[i].y * tanh_fast(gr[i].y + u.y);
                pb += vr[i].z * tanh_fast(gr[i].z + u.z)
                    + vr[i].w * tanh_fast(gr[i].w + u.w);
            }
            float p = pa + pb;
            p += __shfl_xor_sync(0xFFFFFFFFu, p, 4);
            p += __shfl_xor_sync(0xFFFFFFFFu, p, 8);
            p += __shfl_xor_sync(0xFFFFFFFFu, p, 16);
            if (q == 0 && (wb + wq) < WIN) scrow[wb + wq] = p;
        }
    }
    __syncwarp();
    {
        float s0 = scrow[lane];
        float s1 = (lane + 32 < WIN) ? scrow[lane + 32] : -1e30f;
        float mx = warp_max(fmaxf(s0, s1));
        float e0 = __expf(s0 - mx);
        float e1 = (lane + 32 < WIN) ? __expf(s1 - mx) : 0.f;
        float inv = 1.f / warp_sum(e0 + e1);
        float a0 = e0 * inv, a1 = e1 * inv;
        __syncwarp();
        if (lane < WIN) {
            scrow[lane] = a0;
            out[AONSET_OFF + (size_t)tok * WIN + lane] = a0;
        }
        if (lane + 32 < WIN) {
            scrow[lane + 32] = a1;
            out[AONSET_OFF + (size_t)tok * WIN + lane + 32] = a1;
        }
    }
    __syncwarp();

    // ================= Phase 3: onset p-sum -> onset_pred (regs) =================
    float4 opred;
    if (lane < 22) {
        const float4* pb4 = (const float4*)P1 + (size_t)warp * 22 + lane;
        float4 acc = make_float4(0.f, 0.f, 0.f, 0.f);
        #pragma unroll 4
        for (int w = 0; w < WIN; w++) {
            float a = scrow[w];
            float4 p = pb4[(size_t)w * 22];
            acc.x += a * p.x; acc.y += a * p.y; acc.z += a * p.z; acc.w += a * p.w;
        }
        float4 ad = ((const float4*)bl1)[lane];
        opred.x = sigmoid_fast(acc.x + ad.x);
        opred.y = sigmoid_fast(acc.y + ad.y);
        opred.z = sigmoid_fast(acc.z + ad.z);
        opred.w = sigmoid_fast(acc.w + ad.w);
        ((float4*)(out + ONSET_OFF + (size_t)tok * OUTF))[lane] = opred;
    }
    __syncthreads();   // all U (u_o) and P1 (p1) reads complete

    // ================= Phase 4: stage A (feat+onset) and u_c =================
    for (int i = tid; i < AT_TT * 22; i += 512) {
        int tt = i / 22, c = i - tt * 22;
        float4 f = ((const float4*)(out + FEAT_OFF + (size_t)(tok0 + tt) * OUTF))[c];
        int r = c * 4;
        A[(r+0) * APITCH + tt] = f.x;
        A[(r+1) * APITCH + tt] = f.y;
        A[(r+2) * APITCH + tt] = f.z;
        A[(r+3) * APITCH + tt] = f.w;
    }
    if (lane < 22) {
        int r = 88 + lane * 4;
        A[(r+0) * APITCH + warp] = opred.x;
        A[(r+1) * APITCH + warp] = opred.y;
        A[(r+2) * APITCH + warp] = opred.z;
        A[(r+3) * APITCH + warp] = opred.w;
    }
    {
        const float4* usrc = (const float4*)(uc + grow * MODEL);
        float4* udst = (float4*)U;
        #pragma unroll
        for (int i = tid; i < AT_ROWS * 32; i += 512) {
            int r = i >> 5, c = i & 31;
            udst[r * UP4 + c] = usrc[i];
        }
    }
    __syncthreads();

    // ================= Phase 5: GEMM  [16 x 176] @ [176 x 216] =================
    {
        const int s = (tid >= 216);
        const int j = tid - s * 216;
        const bool active = (tid < 432);
        float rv[16];
        if (active) {
            const float* wp;
            int stride;
            if (j < 128) { wp = Wac + j;         stride = MODEL; }
            else         { wp = Wlc + (j - 128); stride = OUTF;  }
            wp += (size_t)(s * 88) * stride;

            unsigned long long acc[8];
            #pragma unroll
            for (int p = 0; p < 8; p++) acc[p] = 0ull;
            const int k0 = s * 88;
            #pragma unroll 4
            for (int k = k0; k < k0 + 88; k++) {
                float w = *wp; wp += stride;
                unsigned long long ww = pkf2(w, w);
                const unsigned long long* row = (const unsigned long long*)(A + k * APITCH);
                #pragma unroll
                for (int p = 0; p < 8; p++) fma2(acc[p], row[p], ww);
            }
            #pragma unroll
            for (int p = 0; p < 8; p++) {
                float2 r = upk(acc[p]);
                rv[2*p] = r.x; rv[2*p+1] = r.y;
            }
            if (s == 1) {
                #pragma unroll
                for (int tt = 0; tt < 16; tt++) part[j * PPITCH + tt] = rv[tt];
            }
        }
        __syncthreads();
        if (active && s == 0) {
            if (j < 128) {
                float bias = bac[j];
                #pragma unroll
                for (int tt = 0; tt < 16; tt++)
                    gc[tt * MODEL + j] = rv[tt] + part[j * PPITCH + tt] + bias;
            } else {
                int m = j - 128;
                float bias = blc[m];
                #pragma unroll
                for (int tt = 0; tt < 16; tt++)
                    xl[tt * OUTF + m] = rv[tt] + part[j * PPITCH + tt] + bias;
            }
        }
    }
    __syncthreads();   // gc/xl written

    // ================= Phase 6: load combine g/v =================
    {
        const float4* gp = (const float4*)(gc + warp * MODEL) + q * 4;
        const float4* vp = (const float4*)vc + q * 4;
        #pragma unroll
        for (int i = 0; i < 4; i++) { gr[i] = gp[i]; vr[i] = vp[i]; }
    }

    // ================= Phase 7: combine scores + softmax =================
    {
        const float4* ubase = (const float4*)U + (size_t)(warp + wq) * UP4 + q * 4;
        #pragma unroll 4
        for (int wb = 0; wb < 64; wb += 4) {
            const float4* ur = ubase + (size_t)wb * UP4;
            float pa = 0.f, pb = 0.f;
            #pragma unroll
            for (int i = 0; i < 4; i++) {
                float4 u = ur[i];
                pa += vr[i].x * tanh_fast(gr[i].x + u.x)
                    + vr[i].y * tanh_fast(gr[i].y + u.y);
                pb += vr[i].z * tanh_fast(gr[i].z + u.z)
                    + vr[i].w * tanh_fast(gr[i].w + u.w);
            }
            float p = pa + pb;
            p += __shfl_xor_sync(0xFFFFFFFFu, p, 4);
            p += __shfl_xor_sync(0xFFFFFFFFu, p, 8);
            p += __shfl_xor_sync(0xFFFFFFFFu, p, 16);
            if (q == 0 && (wb + wq) < WIN) scrow[wb + wq] = p;
        }
    }
    __syncwarp();
    {
        float s0 = scrow[lane];
        float s1 = (lane + 32 < WIN) ? scrow[lane + 32] : -1e30f;
        float mx = warp_max(fmaxf(s0, s1));
        float e0 = __expf(s0 - mx);
        float e1 = (lane + 32 < WIN) ? __expf(s1 - mx) : 0.f;
        float inv = 1.f / warp_sum(e0 + e1);
        float a0 = e0 * inv, a1 = e1 * inv;
        __syncwarp();
        if (lane < WIN) {
            scrow[lane] = a0;
            out[AFRAME_OFF + (size_t)tok * WIN + lane] = a0;
        }
        if (lane + 32 < WIN) {
            scrow[lane + 32] = a1;
            out[AFRAME_OFF + (size_t)tok * WIN + lane + 32] = a1;
        }
    }
    __syncwarp();

    // ================= Phase 8: combine p-sum -> frame_pred =================
    if (lane < 22) {
        const float4* pb4 = (const float4*)P2 + (size_t)warp * 22 + lane;
        float4 acc = make_float4(0.f, 0.f, 0.f, 0.f);
        #pragma unroll 4
        for (int w = 0; w < WIN; w++) {
            float a = scrow[w];
            float4 p = pb4[(size_t)w * 22];
            acc.x += a * p.x; acc.y += a * p.y; acc.z += a * p.z; acc.w += a * p.w;
        }
        float4 ad = ((const float4*)(xl + warp * OUTF))[lane];
        float4 r;
        r.x = sigmoid_fast(acc.x + ad.x);
        r.y = sigmoid_fast(acc.y + ad.y);
        r.z = sigmoid_fast(acc.z + ad.z);
        r.w = sigmoid_fast(acc.w + ad.w);
        ((float4*)(out + FRAME_OFF + (size_t)tok * OUTF))[lane] = r;
    }
}

extern "C" void kernel_launch(void* const* d_in, const int* in_sizes, int n_in,
                              void* d_out, int out_size)
{
    const float* spec = (const float*)d_in[0];
    const float* Wf   = (const float*)d_in[1];
    const float* bf   = (const float*)d_in[2];
    const float* Wao  = (const float*)d_in[3];
    const float* bao  = (const float*)d_in[4];
    const float* vo   = (const float*)d_in[5];
    const float* Wl1  = (const float*)d_in[6];
    const float* bl1  = (const float*)d_in[7];
    const float* Wac  = (const float*)d_in[8];
    const float* bac  = (const float*)d_in[9];
    const float* vc   = (const float*)d_in[10];
    const float* Wlc  = (const float*)d_in[11];
    const float* blc  = (const float*)d_in[12];
    float* out = (float*)d_out;

    float *p_go, *p_uo, *p_uc, *p_p12;
    cudaGetSymbolAddress((void**)&p_go,  g_go);
    cudaGetSymbolAddress((void**)&p_uo,  g_uo);
    cudaGetSymbolAddress((void**)&p_uc,  g_uc);
    cudaGetSymbolAddress((void**)&p_p12, g_p12);

    const int smem_bytes = SM_TOT * 4;   // 113616 B
    cudaFuncSetAttribute(k_fused,
                         cudaFuncAttributeMaxDynamicSharedMemorySize, smem_bytes);

    k1_proj<<<NTOK / K1_TT, 384>>>(spec, Wf, bf, Wao, bao, Wac, Wl1, Wlc, out);
    k_fused<<<NTOK / AT_TT, 512, smem_bytes>>>(
        p_go, p_uo, p_uc, vo, vc, bl1, Wac, bac, Wlc, blc, p_p12, out);
}

// round 12
// speedup vs baseline: 1.0239x; 1.0239x over previous
#include <cuda_runtime.h>
#include <math.h>

#define NBINS 229
#define OUTF  88
#define MODEL 128
#define WSZ   30
#define WIN   61
#define TSEQ  1024
#define NTOK  4096
#define TPAD  1084            // 30 + 1024 + 30
#define PCOLS 176             // P1(88) | P2(88)
#define AT_TT 16              // tokens per attention block
#define AT_ROWS (AT_TT + 2*WSZ)   // 76 staged rows (real)
#define AT_ROWS_AL 80         // allocated rows (windows 61..63 over-read, discarded)
#define UPITCH 132            // padded u row (33 float4)
#define UP4 (UPITCH/4)
#define APITCH 18             // A row pitch (72B, 8-aligned for u64 reads)
#define PPITCH 17             // part row pitch

// smem float offsets (R10 layout)
#define SM_U    0
#define SM_PR   (AT_ROWS_AL * UPITCH)                 // 10560
#define SM_PRSZ 6840                                  // max(76*88=6688, 176*18+216*17=6840)
#define SM_SC   (SM_PR + SM_PRSZ)                     // 17400
#define SM_GC   (SM_SC + AT_TT * 64)                  // +1024
#define SM_XL   (SM_GC + AT_TT * MODEL)               // +2048
#define SM_TOT  (SM_XL + AT_TT * OUTF)                // 21880 floats = 87520 B

// Output layout (floats): frame_pred, a_frame, onset_pred, a_onset, feat_pred
#define FRAME_OFF  0
#define AFRAME_OFF (NTOK*OUTF)
#define ONSET_OFF  (AFRAME_OFF + NTOK*WIN)
#define AONSET_OFF (ONSET_OFF + NTOK*OUTF)
#define FEAT_OFF   (AONSET_OFF + NTOK*WIN)

// Scratch (__device__ globals; zero-initialized at load — guard rows of
// g_uo/g_uc/g_p12 are never written, so they stay zero forever).
__device__ float g_go[NTOK * MODEL];
__device__ float g_uo[4 * TPAD * MODEL];
__device__ float g_uc[4 * TPAD * MODEL];
__device__ float g_p12[4 * TPAD * PCOLS];

__device__ __forceinline__ float tanh_fast(float x) {
    float y; asm("tanh.approx.f32 %0, %1;" : "=f"(y) : "f"(x)); return y;
}
__device__ __forceinline__ float sigmoid_fast(float x) {
    return 1.f / (1.f + __expf(-x));
}
__device__ __forceinline__ unsigned long long pkf2(float lo, float hi) {
    unsigned long long r;
    asm("mov.b64 %0, {%1, %2};" : "=l"(r) : "f"(lo), "f"(hi));
    return r;
}
__device__ __forceinline__ void fma2(unsigned long long& acc,
                                     unsigned long long a, unsigned long long b) {
    asm("fma.rn.f32x2 %0, %1, %2, %0;" : "+l"(acc) : "l"(a), "l"(b));
}
__device__ __forceinline__ float2 upk(unsigned long long v) {
    float2 r;
    asm("mov.b64 {%0, %1}, %2;" : "=f"(r.x), "=f"(r.y) : "l"(v));
    return r;
}
__device__ __forceinline__ void cp_async16(unsigned int smem_addr, const void* gptr) {
    asm volatile("cp.async.cg.shared.global [%0], [%1], 16;"
                 :: "r"(smem_addr), "l"(gptr) : "memory");
}
#define CP_COMMIT() asm volatile("cp.async.commit_group;" ::: "memory")
#define CP_WAIT(n)  asm volatile("cp.async.wait_group %0;" :: "n"(n) : "memory")

__device__ __forceinline__ float warp_sum(float v) {
    v += __shfl_xor_sync(0xFFFFFFFFu, v, 16);
    v += __shfl_xor_sync(0xFFFFFFFFu, v, 8);
    v += __shfl_xor_sync(0xFFFFFFFFu, v, 4);
    v += __shfl_xor_sync(0xFFFFFFFFu, v, 2);
    v += __shfl_xor_sync(0xFFFFFFFFu, v, 1);
    return v;
}
__device__ __forceinline__ float warp_max(float v) {
    v = fmaxf(v, __shfl_xor_sync(0xFFFFFFFFu, v, 16));
    v = fmaxf(v, __shfl_xor_sync(0xFFFFFFFFu, v, 8));
    v = fmaxf(v, __shfl_xor_sync(0xFFFFFFFFu, v, 4));
    v = fmaxf(v, __shfl_xor_sync(0xFFFFFFFFu, v, 2));
    v = fmaxf(v, __shfl_xor_sync(0xFFFFFFFFu, v, 1));
    return v;
}

// ---------------------------------------------------------------------------
// k1: mega projection GEMM  [NTOK x 229] @ [229 x 648], 2 cols per thread
// ---------------------------------------------------------------------------
#define K1_TT 16
__device__ __forceinline__ const float* k1_col_ptr(
    int j, int& stride,
    const float* Wf, const float* Wao, const float* Wac,
    const float* Wl1, const float* Wlc)
{
    if (j < 88)       { stride = OUTF;  return Wf + j; }
    else if (j < 216) { stride = MODEL; return Wao + (j - 88); }
    else if (j < 344) { stride = MODEL; return Wao + NBINS*MODEL + (j - 216); }
    else if (j < 472) { stride = MODEL; return Wac + 176*MODEL  + (j - 344); }
    else if (j < 560) { stride = OUTF;  return Wl1 + (j - 472); }
    else              { stride = OUTF;  return Wlc + 176*OUTF   + (j - 560); }
}

__device__ __forceinline__ void k1_store(
    int j, const float rv[K1_TT], int tok0, size_t row0,
    const float* bf, const float* bao, float* out)
{
    if (j < 88) {
        float bias = bf[j];
        #pragma unroll
        for (int tt = 0; tt < K1_TT; tt++)
            out[FEAT_OFF + (size_t)(tok0 + tt) * OUTF + j] = rv[tt] + bias;
    } else if (j < 216) {
        int m = j - 88;
        float bias = bao[m];
        #pragma unroll
        for (int tt = 0; tt < K1_TT; tt++)
            g_go[(size_t)(tok0 + tt) * MODEL + m] = rv[tt] + bias;
    } else if (j < 344) {
        int m = j - 216;
        #pragma unroll
        for (int tt = 0; tt < K1_TT; tt++)
            g_uo[(row0 + tt) * MODEL + m] = rv[tt];
    } else if (j < 472) {
        int m = j - 344;
        #pragma unroll
        for (int tt = 0; tt < K1_TT; tt++)
            g_uc[(row0 + tt) * MODEL + m] = rv[tt];
    } else if (j < 560) {
        int m = j - 472;
        #pragma unroll
        for (int tt = 0; tt < K1_TT; tt++)
            g_p12[(row0 + tt) * PCOLS + m] = rv[tt];
    } else {
        int m = j - 560 + 88;
        #pragma unroll
        for (int tt = 0; tt < K1_TT; tt++)
            g_p12[(row0 + tt) * PCOLS + m] = rv[tt];
    }
}

__global__ void __launch_bounds__(384) k1_proj(
    const float* __restrict__ spec,
    const float* __restrict__ Wf,  const float* __restrict__ bf,
    const float* __restrict__ Wao, const float* __restrict__ bao,
    const float* __restrict__ Wac,
    const float* __restrict__ Wl1,
    const float* __restrict__ Wlc,
    float* __restrict__ out)
{
    __shared__ __align__(16) float sh[NBINS][20];
    const int tok0 = blockIdx.x * K1_TT;

    for (int idx = threadIdx.x; idx < NBINS * K1_TT; idx += 384) {
        int tt = idx / NBINS;
        int k  = idx - tt * NBINS;
        sh[k][tt] = spec[(size_t)(tok0 + tt) * NBINS + k];
    }
    __syncthreads();

    const int j0 = threadIdx.x;
    if (j0 >= 324) return;
    const int j1 = j0 + 324;

    int st0, st1;
    const float* wp0 = k1_col_ptr(j0, st0, Wf, Wao, Wac, Wl1, Wlc);
    const float* wp1 = k1_col_ptr(j1, st1, Wf, Wao, Wac, Wl1, Wlc);

    unsigned long long acc0[8], acc1[8];
    #pragma unroll
    for (int p = 0; p < 8; p++) { acc0[p] = 0ull; acc1[p] = 0ull; }

    #pragma unroll 2
    for (int k = 0; k < NBINS; k++) {
        float w0 = *wp0; wp0 += st0;
        float w1 = *wp1; wp1 += st1;
        unsigned long long ww0 = pkf2(w0, w0);
        unsigned long long ww1 = pkf2(w1, w1);
        const unsigned long long* row = (const unsigned long long*)&sh[k][0];
        unsigned long long r[8];
        #pragma unroll
        for (int p = 0; p < 8; p++) r[p] = row[p];
        #pragma unroll
        for (int p = 0; p < 8; p++) fma2(acc0[p], r[p], ww0);
        #pragma unroll
        for (int p = 0; p < 8; p++) fma2(acc1[p], r[p], ww1);
    }

    const size_t row0 = (size_t)(tok0 >> 10) * TPAD + WSZ + (tok0 & (TSEQ - 1));
    float rv[K1_TT];
    #pragma unroll
    for (int p = 0; p < 8; p++) {
        float2 r = upk(acc0[p]);
        rv[2*p] = r.x; rv[2*p+1] = r.y;
    }
    k1_store(j0, rv, tok0, row0, bf, bao, out);
    #pragma unroll
    for (int p = 0; p < 8; p++) {
        float2 r = upk(acc1[p]);
        rv[2*p] = r.x; rv[2*p+1] = r.y;
    }
    k1_store(j1, rv, tok0, row0, bf, bao, out);
}

// ---------------------------------------------------------------------------
// k_fused: onset attention -> g_c/xl GEMM -> combine attention.
// cp.async staging with deferred waits: u_c hidden under softmax/p-sum/GEMM,
// p2 hidden under combine scores.
// ---------------------------------------------------------------------------
__global__ void __launch_bounds__(512, 2) k_fused(
    const float* __restrict__ gvo,    // g_go [NTOK][128]
    const float* __restrict__ uo,     // g_uo
    const float* __restrict__ uc,     // g_uc
    const float* __restrict__ vo, const float* __restrict__ vc,
    const float* __restrict__ bl1,
    const float* __restrict__ Wac, const float* __restrict__ bac,
    const float* __restrict__ Wlc, const float* __restrict__ blc,
    const float* __restrict__ ppad,   // g_p12
    float* __restrict__ out)
{
    extern __shared__ __align__(16) float smem[];
    float* U  = smem + SM_U;     // u tile [80][132] (76 real rows)
    float* PR = smem + SM_PR;    // p tile [76][88]  OR  A[176][18]+part[216][17]
    float* sc = smem + SM_SC;    // [16][64]
    float* gc = smem + SM_GC;    // [16][128]
    float* xl = smem + SM_XL;    // [16][88]
    float* A    = PR;
    float* part = PR + 176 * APITCH;

    const unsigned int U_s  = (unsigned int)__cvta_generic_to_shared(U);
    const unsigned int PR_s = (unsigned int)__cvta_generic_to_shared(PR);

    const int tok0 = blockIdx.x * AT_TT;
    const int b    = tok0 >> 10;
    const int t0   = tok0 & (TSEQ - 1);
    const int tid  = threadIdx.x;
    const int warp = tid >> 5;
    const int lane = tid & 31;
    const int q    = lane >> 2;   // 16-dim slice
    const int wq   = lane & 3;    // window within group
    const int tok  = tok0 + warp;

    const size_t grow = (size_t)b * TPAD + t0;

    // ========== Phase 1: cp.async u_o + p1; load onset g/v ==========
    {
        const float4* usrc = (const float4*)(uo + grow * MODEL);
        #pragma unroll
        for (int i = tid; i < AT_ROWS * 32; i += 512) {
            int r = i >> 5, c = i & 31;
            cp_async16(U_s + (unsigned)(r * UP4 + c) * 16u, usrc + i);
        }
        const float4* p1src = (const float4*)(ppad + grow * PCOLS);
        #pragma unroll
        for (int i = tid; i < AT_ROWS * 22; i += 512) {
            int r = i / 22, c = i - r * 22;
            cp_async16(PR_s + (unsigned)i * 16u, p1src + (size_t)r * 44 + c);
        }
    }
    CP_COMMIT();
    float4 gr[4], vr[4];
    {
        const float4* gp = (const float4*)(gvo + (size_t)tok * MODEL) + q * 4;
        const float4* vp = (const float4*)vo + q * 4;
        #pragma unroll
        for (int i = 0; i < 4; i++) { gr[i] = gp[i]; vr[i] = vp[i]; }
    }
    float* scrow = sc + warp * 64;
    CP_WAIT(0);
    __syncthreads();

    // ========== Phase 2: onset scores + softmax + p-sum + onset_pred ==========
    {
        const float4* ubase = (const float4*)U + (size_t)(warp + wq) * UP4 + q * 4;
        #pragma unroll 4
        for (int wb = 0; wb < 64; wb += 4) {
            const float4* ur = ubase + (size_t)wb * UP4;
            float pa = 0.f, pb = 0.f;
            #pragma unroll
            for (int i = 0; i < 4; i++) {
                float4 u = ur[i];
                pa += vr[i].x * tanh_fast(gr[i].x + u.x)
                    + vr[i].y * tanh_fast(gr[i].y + u.y);
                pb += vr[i].z * tanh_fast(gr[i].z + u.z)
                    + vr[i].w * tanh_fast(gr[i].w + u.w);
            }
            float p = pa + pb;
            p += __shfl_xor_sync(0xFFFFFFFFu, p, 4);
            p += __shfl_xor_sync(0xFFFFFFFFu, p, 8);
            p += __shfl_xor_sync(0xFFFFFFFFu, p, 16);
            if (q == 0 && (wb + wq) < WIN) scrow[wb + wq] = p;
        }
    }
    __syncwarp();
    {
        float s0 = scrow[lane];
        float s1 = (lane + 32 < WIN) ? scrow[lane + 32] : -1e30f;
        float mx = warp_max(fmaxf(s0, s1));
        float e0 = __expf(s0 - mx);
        float e1 = (lane + 32 < WIN) ? __expf(s1 - mx) : 0.f;
        float inv = 1.f / warp_sum(e0 + e1);
        float a0 = e0 * inv, a1 = e1 * inv;
        __syncwarp();
        if (lane < WIN) {
            scrow[lane] = a0;
            out[AONSET_OFF + (size_t)tok * WIN + lane] = a0;
        }
        if (lane + 32 < WIN) {
            scrow[lane + 32] = a1;
            out[AONSET_OFF + (size_t)tok * WIN + lane + 32] = a1;
        }
    }
    __syncwarp();

    float4 opred;
    if (lane < 22) {
        const float4* pb4 = (const float4*)PR + (size_t)warp * 22 + lane;
        float4 acc = make_float4(0.f, 0.f, 0.f, 0.f);
        #pragma unroll 4
        for (int w = 0; w < WIN; w++) {
            float a = scrow[w];
            float4 p = pb4[(size_t)w * 22];
            acc.x += a * p.x; acc.y += a * p.y; acc.z += a * p.z; acc.w += a * p.w;
        }
        float4 ad = ((const float4*)bl1)[lane];
        opred.x = sigmoid_fast(acc.x + ad.x);
        opred.y = sigmoid_fast(acc.y + ad.y);
        opred.z = sigmoid_fast(acc.z + ad.z);
        opred.w = sigmoid_fast(acc.w + ad.w);
        ((float4*)(out + ONSET_OFF + (size_t)tok * OUTF))[lane] = opred;
    }
    __syncthreads();   // all U (u_o) and PR (p1) reads complete

    // ========== Phase 3: issue u_c cp.async (deferred); stage A ==========
    {
        const float4* usrc = (const float4*)(uc + grow * MODEL);
        #pragma unroll
        for (int i = tid; i < AT_ROWS * 32; i += 512) {
            int r = i >> 5, c = i & 31;
            cp_async16(U_s + (unsigned)(r * UP4 + c) * 16u, usrc + i);
        }
    }
    CP_COMMIT();   // group: u_c (waited before combine scores)

    for (int i = tid; i < AT_TT * 22; i += 512) {
        int tt = i / 22, c = i - tt * 22;
        float4 f = ((const float4*)(out + FEAT_OFF + (size_t)(tok0 + tt) * OUTF))[c];
        int r = c * 4;
        A[(r+0) * APITCH + tt] = f.x;
        A[(r+1) * APITCH + tt] = f.y;
        A[(r+2) * APITCH + tt] = f.z;
        A[(r+3) * APITCH + tt] = f.w;
    }
    if (lane < 22) {
        int r = 88 + lane * 4;
        A[(r+0) * APITCH + warp] = opred.x;
        A[(r+1) * APITCH + warp] = opred.y;
        A[(r+2) * APITCH + warp] = opred.z;
        A[(r+3) * APITCH + warp] = opred.w;
    }
    __syncthreads();   // A ready (u_c still in flight)

    // ========== Phase 4: GEMM  [16 x 176] @ [176 x 216] ==========
    {
        const int s = (tid >= 216);
        const int j = tid - s * 216;
        const bool active = (tid < 432);
        float rv[16];
        if (active) {
            const float* wp;
            int stride;
            if (j < 128) { wp = Wac + j;         stride = MODEL; }
            else         { wp = Wlc + (j - 128); stride = OUTF;  }
            wp += (size_t)(s * 88) * stride;

            unsigned long long acc[8];
            #pragma unroll
            for (int p = 0; p < 8; p++) acc[p] = 0ull;
            const int k0 = s * 88;
            #pragma unroll 4
            for (int k = k0; k < k0 + 88; k++) {
                float w = *wp; wp += stride;
                unsigned long long ww = pkf2(w, w);
                const unsigned long long* row = (const unsigned long long*)(A + k * APITCH);
                #pragma unroll
                for (int p = 0; p < 8; p++) fma2(acc[p], row[p], ww);
            }
            #pragma unroll
            for (int p = 0; p < 8; p++) {
                float2 r = upk(acc[p]);
                rv[2*p] = r.x; rv[2*p+1] = r.y;
            }
            if (s == 1) {
                #pragma unroll
                for (int tt = 0; tt < 16; tt++) part[j * PPITCH + tt] = rv[tt];
            }
        }
        __syncthreads();
        if (active && s == 0) {
            if (j < 128) {
                float bias = bac[j];
                #pragma unroll
                for (int tt = 0; tt < 16; tt++)
                    gc[tt * MODEL + j] = rv[tt] + part[j * PPITCH + tt] + bias;
            } else {
                int m = j - 128;
                float bias = blc[m];
                #pragma unroll
                for (int tt = 0; tt < 16; tt++)
                    xl[tt * OUTF + m] = rv[tt] + part[j * PPITCH + tt] + bias;
            }
        }
    }
    __syncthreads();   // gc/xl written; A/part reads done -> PR free

    // ========== Phase 5: issue p2 cp.async; combine scores ==========
    {
        const float4* p2src = (const float4*)(ppad + grow * PCOLS + 88);
        #pragma unroll
        for (int i = tid; i < AT_ROWS * 22; i += 512) {
            int r = i / 22, c = i - r * 22;
            cp_async16(PR_s + (unsigned)i * 16u, p2src + (size_t)r * 44 + c);
        }
    }
    CP_COMMIT();   // group: p2 (waited after combine scores)
    {
        const float4* gp = (const float4*)(gc + warp * MODEL) + q * 4;
        const float4* vp = (const float4*)vc + q * 4;
        #pragma unroll
        for (int i = 0; i < 4; i++) { gr[i] = gp[i]; vr[i] = vp[i]; }
    }
    CP_WAIT(1);        // u_c arrived (p2 may still be pending)
    __syncthreads();   // u_c visible to all threads

    {
        const float4* ubase = (const float4*)U + (size_t)(warp + wq) * UP4 + q * 4;
        #pragma unroll 4
        for (int wb = 0; wb < 64; wb += 4) {
            const float4* ur = ubase + (size_t)wb * UP4;
            float pa = 0.f, pb = 0.f;
            #pragma unroll
            for (int i = 0; i < 4; i++) {
                float4 u = ur[i];
                pa += vr[i].x * tanh_fast(gr[i].x + u.x)
                    + vr[i].y * tanh_fast(gr[i].y + u.y);
                pb += vr[i].z * tanh_fast(gr[i].z + u.z)
                    + vr[i].w * tanh_fast(gr[i].w + u.w);
            }
            float p = pa + pb;
            p += __shfl_xor_sync(0xFFFFFFFFu, p, 4);
            p += __shfl_xor_sync(0xFFFFFFFFu, p, 8);
            p += __shfl_xor_sync(0xFFFFFFFFu, p, 16);
            if (q == 0 && (wb + wq) < WIN) scrow[wb + wq] = p;
        }
    }
    __syncwarp();
    {
        float s0 = scrow[lane];
        float s1 = (lane + 32 < WIN) ? scrow[lane + 32] : -1e30f;
        float mx = warp_max(fmaxf(s0, s1));
        float e0 = __expf(s0 - mx);
        float e1 = (lane + 32 < WIN) ? __expf(s1 - mx) : 0.f;
        float inv = 1.f / warp_sum(e0 + e1);
        float a0 = e0 * inv, a1 = e1 * inv;
        __syncwarp();
        if (lane < WIN) {
            scrow[lane] = a0;
            out[AFRAME_OFF + (size_t)tok * WIN + lane] = a0;
        }
        if (lane + 32 < WIN) {
            scrow[lane + 32] = a1;
            out[AFRAME_OFF + (size_t)tok * WIN + lane + 32] = a1;
        }
    }
    CP_WAIT(0);        // p2 arrived
    __syncthreads();   // p2 visible

    // ========== Phase 6: combine p-sum -> frame_pred ==========
    if (lane < 22) {
        const float4* pb4 = (const float4*)PR + (size_t)warp * 22 + lane;
        float4 acc = make_float4(0.f, 0.f, 0.f, 0.f);
        #pragma unroll 4
        for (int w = 0; w < WIN; w++) {
            float a = scrow[w];
            float4 p = pb4[(size_t)w * 22];
            acc.x += a * p.x; acc.y += a * p.y; acc.z += a * p.z; acc.w += a * p.w;
        }
        float4 ad = ((const float4*)(xl + warp * OUTF))[lane];
        float4 r;
        r.x = sigmoid_fast(acc.x + ad.x);
        r.y = sigmoid_fast(acc.y + ad.y);
        r.z = sigmoid_fast(acc.z + ad.z);
        r.w = sigmoid_fast(acc.w + ad.w);
        ((float4*)(out + FRAME_OFF + (size_t)tok * OUTF))[lane] = r;
    }
}

extern "C" void kernel_launch(void* const* d_in, const int* in_sizes, int n_in,
                              void* d_out, int out_size)
{
    const float* spec = (const float*)d_in[0];
    const float* Wf   = (const float*)d_in[1];
    const float* bf   = (const float*)d_in[2];
    const float* Wao  = (const float*)d_in[3];
    const float* bao  = (const float*)d_in[4];
    const float* vo   = (const float*)d_in[5];
    const float* Wl1  = (const float*)d_in[6];
    const float* bl1  = (const float*)d_in[7];
    const float* Wac  = (const float*)d_in[8];
    const float* bac  = (const float*)d_in[9];
    const float* vc   = (const float*)d_in[10];
    const float* Wlc  = (const float*)d_in[11];
    const float* blc  = (const float*)d_in[12];
    float* out = (float*)d_out;

    float *p_go, *p_uo, *p_uc, *p_p12;
    cudaGetSymbolAddress((void**)&p_go,  g_go);
    cudaGetSymbolAddress((void**)&p_uo,  g_uo);
    cudaGetSymbolAddress((void**)&p_uc,  g_uc);
    cudaGetSymbolAddress((void**)&p_p12, g_p12);

    const int smem_bytes = SM_TOT * 4;   // 87520 B
    cudaFuncSetAttribute(k_fused,
                         cudaFuncAttributeMaxDynamicSharedMemorySize, smem_bytes);

    k1_proj<<<NTOK / K1_TT, 384>>>(spec, Wf, bf, Wao, bao, Wac, Wl1, Wlc, out);
    k_fused<<<NTOK / AT_TT, 512, smem_bytes>>>(
        p_go, p_uo, p_uc, vo, vc, bl1, Wac, bac, Wlc, blc, p_p12, out);
}